// round 6
// baseline (speedup 1.0000x reference)
#include <cuda_runtime.h>
#include <cuda_bf16.h>
#include <cstdint>

// SoftmaxRefMatcher: persistent mma.sync bf16 hi/lo GEMM + fused fixed-shift softmax.
// R6: RAW-free 3-sweep MMA ordering; merged finish kernel; gemm at launch idx 3.
// BW=8, C=64, N=256, HW=65536, WINDOW=4 -> B=2, NW=6, 12 (w,kh) groups.

#define CK     64
#define NKP    256
#define HW     65536
#define NW     6
#define TPX    128
#define NTILE  512
#define NGRP   12
#define CPG    49
#define NCTA   (NGRP * CPG)     // 588

__device__ __align__(256) __nv_bfloat16 g_Ahi[NW * NKP * CK];
__device__ __align__(256) __nv_bfloat16 g_Alo[NW * NKP * CK];
__device__ __align__(256) __nv_bfloat16 g_Bhi[2 * HW * CK];
__device__ __align__(256) __nv_bfloat16 g_Blo[2 * HW * CK];
__device__ __align__(256) float g_part[NW * NKP * NTILE * 2];   // [row][tile][{sum,su}]

__device__ __forceinline__ uint32_t smem_u32(const void* p) {
    uint32_t a;
    asm("{ .reg .u64 t; cvta.to.shared.u64 t, %1; cvt.u32.u64 %0, t; }" : "=r"(a) : "l"(p));
    return a;
}
#define LDSM4(R, addr) \
    asm volatile("ldmatrix.sync.aligned.m8n8.x4.shared.b16 {%0,%1,%2,%3}, [%4];" \
        : "=r"((R)[0]), "=r"((R)[1]), "=r"((R)[2]), "=r"((R)[3]) : "r"(addr))
#define MMA16816(D, A, b0, b1) \
    asm volatile("mma.sync.aligned.m16n8k16.row.col.f32.bf16.bf16.f32 " \
        "{%0,%1,%2,%3}, {%4,%5,%6,%7}, {%8,%9}, {%0,%1,%2,%3};" \
        : "+f"((D)[0]), "+f"((D)[1]), "+f"((D)[2]), "+f"((D)[3]) \
        : "r"((A)[0]), "r"((A)[1]), "r"((A)[2]), "r"((A)[3]), "r"(b0), "r"(b1))
#define CP16(dst, src) \
    asm volatile("cp.async.cg.shared.global [%0], [%1], 16;" :: "r"(dst), "l"(src))
#define CP_COMMIT() asm volatile("cp.async.commit_group;" ::: "memory")
#define CP_WAIT1()  asm volatile("cp.async.wait_group 1;" ::: "memory")

__device__ __forceinline__ void split_bf16(float x, __nv_bfloat16& hi, __nv_bfloat16& lo) {
    hi = __float2bfloat16(x);
    lo = __float2bfloat16(x - __bfloat162float(hi));
}

// ---------------------------------------------------------------- tgt prep
__global__ __launch_bounds__(128) void k_prep_tgt(const float* __restrict__ kd) {
    int idx = blockIdx.x;                   // 0..11
    int tid = threadIdx.x;
    int w = idx >> 1;
    int n = (idx & 1) * 128 + tid;
    int f = (w / 3) * 4 + (w % 3) + 1;
    const float* src = kd + f * CK * NKP + n;
    float v[CK]; float ss = 0.f;
    #pragma unroll
    for (int c = 0; c < CK; c++) { v[c] = src[c * NKP]; ss += v[c] * v[c]; }
    float inv = 1.f / fmaxf(sqrtf(ss), 1e-12f);
    int base = (w * NKP + n) * CK;
    #pragma unroll
    for (int c = 0; c < CK; c++) {
        __nv_bfloat16 hi, lo; split_bf16(v[c] * inv, hi, lo);
        g_Ahi[base + c] = hi; g_Alo[base + c] = lo;
    }
}

// ---------------------------------------------------------------- src prep (half grid per launch)
__global__ __launch_bounds__(128) void k_prep_src(const float* __restrict__ dd, int blk0) {
    __shared__ uint32_t sH[128 * 33], sL[128 * 33];
    int bid = blockIdx.x + blk0;
    int tid = threadIdx.x;
    int pidx = bid * 128 + tid;
    int b = pidx >> 16;
    const float* src = dd + (size_t)(b * 4) * CK * HW + (pidx & (HW - 1));
    float v[CK]; float ss = 0.f;
    #pragma unroll
    for (int c = 0; c < CK; c++) { v[c] = src[(size_t)c * HW]; ss += v[c] * v[c]; }
    float inv = 1.f / fmaxf(sqrtf(ss), 1e-12f);
    #pragma unroll
    for (int j = 0; j < 32; j++) {
        __nv_bfloat16 h0, l0, h1, l1;
        split_bf16(v[2 * j] * inv, h0, l0);
        split_bf16(v[2 * j + 1] * inv, h1, l1);
        sH[tid * 33 + j] = (uint32_t)__bfloat16_as_ushort(h0) | ((uint32_t)__bfloat16_as_ushort(h1) << 16);
        sL[tid * 33 + j] = (uint32_t)__bfloat16_as_ushort(l0) | ((uint32_t)__bfloat16_as_ushort(l1) << 16);
    }
    __syncthreads();
    uint32_t* oH = reinterpret_cast<uint32_t*>(g_Bhi) + (size_t)bid * 128 * 32;
    uint32_t* oL = reinterpret_cast<uint32_t*>(g_Blo) + (size_t)bid * 128 * 32;
    #pragma unroll
    for (int i = 0; i < 32; i++) {
        int u = tid + i * 128;
        int mm = u >> 5, j = u & 31;
        oH[u] = sH[mm * 33 + j];
        oL[u] = sL[mm * 33 + j];
    }
}

// ---------------------------------------------------------------- persistent GEMM + softmax
#define SM_A_H 0
#define SM_A_L 16384
#define SM_B(buf) (32768 + (buf) * 32768)
#define SM_RED 98304
#define SM_TOT (98304 + 2048)

__global__ void __launch_bounds__(256, 2) k_gemm() {
    extern __shared__ char smem[];
    uint32_t sb = smem_u32(smem);
    float* sRed = (float*)(smem + SM_RED);
    int tid = threadIdx.x;
    int cta = blockIdx.x;
    int grp = cta % NGRP, j = cta / NGRP;
    int w = grp >> 1, kh = grp & 1, b = w / 3;
    int t0 = (j * NTILE) / CPG, t1 = ((j + 1) * NTILE) / CPG;

    // ---- prefetch A (once) + B(t0) ----
    {
        const __nv_bfloat16* gAH = g_Ahi + (size_t)(w * NKP + kh * 128) * CK;
        const __nv_bfloat16* gAL = g_Alo + (size_t)(w * NKP + kh * 128) * CK;
        #pragma unroll
        for (int i = 0; i < 8; i++) {
            int ch = tid + i * 256;
            int reg = ch >> 10, c2 = ch & 1023;
            int row = c2 >> 3, c = c2 & 7;
            const __nv_bfloat16* src = (reg ? gAL : gAH) + row * CK + c * 8;
            uint32_t dst = sb + (reg ? SM_A_L : SM_A_H) + row * 128 + (((c ^ (row & 7))) << 4);
            CP16(dst, (const void*)src);
        }
    }
    const __nv_bfloat16* gBH = g_Bhi + (size_t)b * HW * CK;
    const __nv_bfloat16* gBL = g_Blo + (size_t)b * HW * CK;
    auto prefB = [&](int buf, int t) {
        #pragma unroll
        for (int i = 0; i < 8; i++) {
            int ch = tid + i * 256;
            int reg = ch >> 10, c2 = ch & 1023;
            int row = c2 >> 3, c = c2 & 7;
            const __nv_bfloat16* src = (reg ? gBL : gBH) + (size_t)(t * TPX + row) * CK + c * 8;
            uint32_t dst = sb + SM_B(buf) + reg * 16384 + row * 128 + (((c ^ (row & 7))) << 4);
            CP16(dst, (const void*)src);
        }
    };
    prefB(0, t0);
    CP_COMMIT();

    // ---- per-warp fragment addressing ----
    int lane = tid & 31, wid = tid >> 5;
    int m0 = (wid & 3) * 32, n0 = (wid >> 2) * 64, wn = wid >> 2;
    int aRow = (lane & 7) + ((lane >> 3) & 1) * 8;
    int aCh  = (lane >> 4) & 1;
    int bRow = (lane & 7) + ((lane >> 4) & 1) * 8;
    int bCh  = (lane >> 3) & 1;
    int rA0 = m0 + aRow, rA1 = rA0 + 16;
    uint32_t aH0 = sb + SM_A_H + rA0 * 128, aH1 = sb + SM_A_H + rA1 * 128;
    uint32_t aL0 = sb + SM_A_L + rA0 * 128, aL1 = sb + SM_A_L + rA1 * 128;
    int xA0 = rA0 & 7, xA1 = rA1 & 7;
    uint32_t bOff[4]; int xB[4];
    #pragma unroll
    for (int q = 0; q < 4; q++) {
        int rB = n0 + q * 16 + bRow;
        bOff[q] = rB * 128; xB[q] = rB & 7;
    }
    int g = lane >> 2, t4 = lane & 3;
    const float K1 = 144.2695041f;          // 100 * log2(e)

    int buf = 0;
    for (int t = t0; t < t1; t++) {
        if (t + 1 < t1) prefB(buf ^ 1, t + 1);
        CP_COMMIT();
        CP_WAIT1();
        __syncthreads();

        float acc[2][8][4];
        #pragma unroll
        for (int i = 0; i < 2; i++)
            #pragma unroll
            for (int nt = 0; nt < 8; nt++)
                #pragma unroll
                for (int q = 0; q < 4; q++) acc[i][nt][q] = 0.f;

        uint32_t bB = sb + SM_B(buf);
        #pragma unroll
        for (int ks = 0; ks < 4; ks++) {
            uint32_t A0h[4], A1h[4], A0l[4], A1l[4], Bf[4][4];
            int chA = aCh + 2 * ks;
            LDSM4(A0h, aH0 + ((chA ^ xA0) << 4));
            LDSM4(A1h, aH1 + ((chA ^ xA1) << 4));
            LDSM4(A0l, aL0 + ((chA ^ xA0) << 4));
            LDSM4(A1l, aL1 + ((chA ^ xA1) << 4));
            int chB = bCh + 2 * ks;
            #pragma unroll
            for (int q = 0; q < 4; q++) LDSM4(Bf[q], bB + bOff[q] + ((chB ^ xB[q]) << 4));
            // sweep 1: hi*hi — 16 MMAs, all-distinct accumulators
            #pragma unroll
            for (int nt = 0; nt < 8; nt++) {
                uint32_t b0 = Bf[nt >> 1][(nt & 1) * 2];
                uint32_t b1 = Bf[nt >> 1][(nt & 1) * 2 + 1];
                MMA16816(acc[0][nt], A0h, b0, b1);
                MMA16816(acc[1][nt], A1h, b0, b1);
            }
            // sweep 2: lo*hi — same accs, >=16 MMAs since last write
            #pragma unroll
            for (int nt = 0; nt < 8; nt++) {
                uint32_t b0 = Bf[nt >> 1][(nt & 1) * 2];
                uint32_t b1 = Bf[nt >> 1][(nt & 1) * 2 + 1];
                MMA16816(acc[0][nt], A0l, b0, b1);
                MMA16816(acc[1][nt], A1l, b0, b1);
            }
            // reload B frags with lo half
            #pragma unroll
            for (int q = 0; q < 4; q++) LDSM4(Bf[q], bB + 16384 + bOff[q] + ((chB ^ xB[q]) << 4));
            // sweep 3: hi*lo
            #pragma unroll
            for (int nt = 0; nt < 8; nt++) {
                uint32_t b0 = Bf[nt >> 1][(nt & 1) * 2];
                uint32_t b1 = Bf[nt >> 1][(nt & 1) * 2 + 1];
                MMA16816(acc[0][nt], A0h, b0, b1);
                MMA16816(acc[1][nt], A1h, b0, b1);
            }
        }

        // ---- fused softmax epilogue ----
        #pragma unroll
        for (int mt = 0; mt < 2; mt++) {
            float s0 = 0.f, u0 = 0.f, s1 = 0.f, u1 = 0.f;
            #pragma unroll
            for (int nt = 0; nt < 8; nt++) {
                float col = (float)(n0 + nt * 8 + t4 * 2);
                float e0, e1, e2, e3;
                asm("ex2.approx.ftz.f32 %0, %1;" : "=f"(e0) : "f"(fmaf(acc[mt][nt][0], K1, -K1)));
                asm("ex2.approx.ftz.f32 %0, %1;" : "=f"(e1) : "f"(fmaf(acc[mt][nt][1], K1, -K1)));
                asm("ex2.approx.ftz.f32 %0, %1;" : "=f"(e2) : "f"(fmaf(acc[mt][nt][2], K1, -K1)));
                asm("ex2.approx.ftz.f32 %0, %1;" : "=f"(e3) : "f"(fmaf(acc[mt][nt][3], K1, -K1)));
                s0 += e0 + e1;  u0 = fmaf(e0, col, u0); u0 = fmaf(e1, col + 1.f, u0);
                s1 += e2 + e3;  u1 = fmaf(e2, col, u1); u1 = fmaf(e3, col + 1.f, u1);
            }
            #pragma unroll
            for (int d = 1; d <= 2; d <<= 1) {
                s0 += __shfl_xor_sync(0xFFFFFFFF, s0, d);
                u0 += __shfl_xor_sync(0xFFFFFFFF, u0, d);
                s1 += __shfl_xor_sync(0xFFFFFFFF, s1, d);
                u1 += __shfl_xor_sync(0xFFFFFFFF, u1, d);
            }
            if (t4 == 0) {
                int r = m0 + mt * 16 + g;
                sRed[r * 4 + wn * 2 + 0] = s0;
                sRed[r * 4 + wn * 2 + 1] = u0;
                sRed[(r + 8) * 4 + wn * 2 + 0] = s1;
                sRed[(r + 8) * 4 + wn * 2 + 1] = u1;
            }
        }
        __syncthreads();
        if (tid < 128) {
            float s = sRed[tid * 4 + 0] + sRed[tid * 4 + 2];
            float u = sRed[tid * 4 + 1] + sRed[tid * 4 + 3];
            size_t row = (size_t)w * NKP + kh * 128 + tid;
            g_part[(row * NTILE + t) * 2 + 0] = s;
            g_part[(row * NTILE + t) * 2 + 1] = u;
        }
        __syncthreads();
        buf ^= 1;
    }
}

// ---------------------------------------------------------------- reduce + tail merged
__global__ __launch_bounds__(256) void k_finish(const float* __restrict__ scores,
                                                float* __restrict__ out) {
    if (blockIdx.x < 192) {
        int row = blockIdx.x * 8 + (threadIdx.x >> 5);
        int lane = threadIdx.x & 31;
        const float4* p = (const float4*)(g_part + (size_t)row * NTILE * 2);
        float s = 0.f, u = 0.f, v = 0.f;
        #pragma unroll
        for (int i = 0; i < 8; i++) {
            int idx = lane + i * 32;
            float4 q = p[idx];
            float sp = q.x + q.z;
            s += sp;
            u += q.y + q.w + 128.f * q.z;
            v = fmaf((float)idx, sp, v);
        }
        #pragma unroll
        for (int d = 16; d > 0; d >>= 1) {
            s += __shfl_xor_sync(0xFFFFFFFF, s, d);
            u += __shfl_xor_sync(0xFFFFFFFF, u, d);
            v += __shfl_xor_sync(0xFFFFFFFF, v, d);
        }
        if (lane == 0) {
            float inv = 1.f / s;
            out[row * 2 + 0] = u * inv;
            out[row * 2 + 1] = v * inv;
        }
    } else {
        int w = blockIdx.x - 192, n = threadIdx.x;
        int f = (w / 3) * 4 + (w % 3) + 1;
        out[3072 + w * NKP + n] = scores[f * NKP + n];
        if (n == 0) {
            out[4608 + w] = (float)f;
            out[4614 + w] = (float)((w / 3) * 4);
        }
    }
}

extern "C" void kernel_launch(void* const* d_in, const int* in_sizes, int n_in,
                              void* d_out, int out_size) {
    (void)in_sizes; (void)n_in; (void)out_size;
    const float* scores = (const float*)d_in[0];
    const float* kd     = (const float*)d_in[1];
    const float* dd     = (const float*)d_in[2];
    float* out = (float*)d_out;

    cudaFuncSetAttribute(k_gemm, cudaFuncAttributeMaxDynamicSharedMemorySize, SM_TOT);

    k_prep_tgt<<<NGRP, 128>>>(kd);          // launch 0
    k_prep_src<<<512, 128>>>(dd, 0);        // launch 1
    k_prep_src<<<512, 128>>>(dd, 512);      // launch 2
    k_gemm<<<NCTA, 256, SM_TOT>>>();        // launch 3  (ncu lands here)
    k_finish<<<198, 256>>>(scores, out);    // launch 4
}

// round 7
// speedup vs baseline: 1.4884x; 1.4884x over previous
#include <cuda_runtime.h>
#include <cuda_bf16.h>
#include <cstdint>

// SoftmaxRefMatcher: persistent mma.sync bf16 hi/lo GEMM + fused fixed-shift softmax.
// R7: CTA split into two independent 4-warp pipelines (named barriers, no __syncthreads
// in loop, no smem reduction) to de-phase-lock tensor vs epilogue work.
// BW=8, C=64, N=256, HW=65536, WINDOW=4 -> B=2, NW=6, 12 (w,kh) groups.

#define CK     64
#define NKP    256
#define HW     65536
#define NW     6
#define TPX    128
#define NTILE  512
#define NGRP   12
#define CPG    49
#define NCTA   (NGRP * CPG)     // 588

__device__ __align__(256) __nv_bfloat16 g_Ahi[NW * NKP * CK];
__device__ __align__(256) __nv_bfloat16 g_Alo[NW * NKP * CK];
__device__ __align__(256) __nv_bfloat16 g_Bhi[2 * HW * CK];
__device__ __align__(256) __nv_bfloat16 g_Blo[2 * HW * CK];
// [row][tile][{s_half0, u_half0, s_half1, u_half1}]
__device__ __align__(256) float g_part[NW * NKP * NTILE * 4];

__device__ __forceinline__ uint32_t smem_u32(const void* p) {
    uint32_t a;
    asm("{ .reg .u64 t; cvta.to.shared.u64 t, %1; cvt.u32.u64 %0, t; }" : "=r"(a) : "l"(p));
    return a;
}
#define LDSM4(R, addr) \
    asm volatile("ldmatrix.sync.aligned.m8n8.x4.shared.b16 {%0,%1,%2,%3}, [%4];" \
        : "=r"((R)[0]), "=r"((R)[1]), "=r"((R)[2]), "=r"((R)[3]) : "r"(addr))
#define MMA16816(D, A, b0, b1) \
    asm volatile("mma.sync.aligned.m16n8k16.row.col.f32.bf16.bf16.f32 " \
        "{%0,%1,%2,%3}, {%4,%5,%6,%7}, {%8,%9}, {%0,%1,%2,%3};" \
        : "+f"((D)[0]), "+f"((D)[1]), "+f"((D)[2]), "+f"((D)[3]) \
        : "r"((A)[0]), "r"((A)[1]), "r"((A)[2]), "r"((A)[3]), "r"(b0), "r"(b1))
#define CP16(dst, src) \
    asm volatile("cp.async.cg.shared.global [%0], [%1], 16;" :: "r"(dst), "l"(src))
#define CP_COMMIT() asm volatile("cp.async.commit_group;" ::: "memory")
#define CP_WAIT1()  asm volatile("cp.async.wait_group 1;" ::: "memory")
#define BARH(id)    asm volatile("bar.sync %0, 128;" :: "r"(id) : "memory")

__device__ __forceinline__ void split_bf16(float x, __nv_bfloat16& hi, __nv_bfloat16& lo) {
    hi = __float2bfloat16(x);
    lo = __float2bfloat16(x - __bfloat162float(hi));
}

// ---------------------------------------------------------------- tgt prep
__global__ __launch_bounds__(128) void k_prep_tgt(const float* __restrict__ kd) {
    int idx = blockIdx.x;                   // 0..11
    int tid = threadIdx.x;
    int w = idx >> 1;
    int n = (idx & 1) * 128 + tid;
    int f = (w / 3) * 4 + (w % 3) + 1;
    const float* src = kd + f * CK * NKP + n;
    float v[CK]; float ss = 0.f;
    #pragma unroll
    for (int c = 0; c < CK; c++) { v[c] = src[c * NKP]; ss += v[c] * v[c]; }
    float inv = 1.f / fmaxf(sqrtf(ss), 1e-12f);
    int base = (w * NKP + n) * CK;
    #pragma unroll
    for (int c = 0; c < CK; c++) {
        __nv_bfloat16 hi, lo; split_bf16(v[c] * inv, hi, lo);
        g_Ahi[base + c] = hi; g_Alo[base + c] = lo;
    }
}

// ---------------------------------------------------------------- src prep (half grid per launch)
__global__ __launch_bounds__(128) void k_prep_src(const float* __restrict__ dd, int blk0) {
    __shared__ uint32_t sH[128 * 33], sL[128 * 33];
    int bid = blockIdx.x + blk0;
    int tid = threadIdx.x;
    int pidx = bid * 128 + tid;
    int b = pidx >> 16;
    const float* src = dd + (size_t)(b * 4) * CK * HW + (pidx & (HW - 1));
    float v[CK]; float ss = 0.f;
    #pragma unroll
    for (int c = 0; c < CK; c++) { v[c] = src[(size_t)c * HW]; ss += v[c] * v[c]; }
    float inv = 1.f / fmaxf(sqrtf(ss), 1e-12f);
    #pragma unroll
    for (int j = 0; j < 32; j++) {
        __nv_bfloat16 h0, l0, h1, l1;
        split_bf16(v[2 * j] * inv, h0, l0);
        split_bf16(v[2 * j + 1] * inv, h1, l1);
        sH[tid * 33 + j] = (uint32_t)__bfloat16_as_ushort(h0) | ((uint32_t)__bfloat16_as_ushort(h1) << 16);
        sL[tid * 33 + j] = (uint32_t)__bfloat16_as_ushort(l0) | ((uint32_t)__bfloat16_as_ushort(l1) << 16);
    }
    __syncthreads();
    uint32_t* oH = reinterpret_cast<uint32_t*>(g_Bhi) + (size_t)bid * 128 * 32;
    uint32_t* oL = reinterpret_cast<uint32_t*>(g_Blo) + (size_t)bid * 128 * 32;
    #pragma unroll
    for (int i = 0; i < 32; i++) {
        int u = tid + i * 128;
        int mm = u >> 5, j = u & 31;
        oH[u] = sH[mm * 33 + j];
        oL[u] = sL[mm * 33 + j];
    }
}

// ---------------------------------------------------------------- persistent GEMM + softmax
// smem: AH 16K | AL 16K | half0 {buf0 hi/lo 16K, buf1 16K} | half1 {32K} = 96K
#define SM_A_H 0
#define SM_A_L 16384
#define SM_B(half, buf) (32768 + (half) * 32768 + (buf) * 16384)
#define SM_TOT 98304

__global__ void __launch_bounds__(256, 2) k_gemm() {
    extern __shared__ char smem[];
    uint32_t sb = smem_u32(smem);
    int tid = threadIdx.x;
    int cta = blockIdx.x;
    int grp = cta % NGRP, j = cta / NGRP;
    int w = grp >> 1, kh = grp & 1, b = w / 3;
    int t0 = (j * NTILE) / CPG, t1 = ((j + 1) * NTILE) / CPG;

    int lane = tid & 31, wid = tid >> 5;
    int half = tid >> 7;                   // warps 0-3 -> half 0, warps 4-7 -> half 1
    int h = tid & 127;                     // tid within half
    int n0 = half * 64;
    int barid = 1 + half;

    // ---- prefetch A (once, whole CTA) ----
    {
        const __nv_bfloat16* gAH = g_Ahi + (size_t)(w * NKP + kh * 128) * CK;
        const __nv_bfloat16* gAL = g_Alo + (size_t)(w * NKP + kh * 128) * CK;
        #pragma unroll
        for (int i = 0; i < 8; i++) {
            int ch = tid + i * 256;
            int reg = ch >> 10, c2 = ch & 1023;
            int row = c2 >> 3, c = c2 & 7;
            const __nv_bfloat16* src = (reg ? gAL : gAH) + row * CK + c * 8;
            uint32_t dst = sb + (reg ? SM_A_L : SM_A_H) + row * 128 + (((c ^ (row & 7))) << 4);
            CP16(dst, (const void*)src);
        }
    }
    const __nv_bfloat16* gBH = g_Bhi + (size_t)b * HW * CK;
    const __nv_bfloat16* gBL = g_Blo + (size_t)b * HW * CK;
    // per-half B prefetch: 64 px rows x (hi+lo) = 16KB by 128 threads, 8 chunks each
    auto prefB = [&](int buf, int t) {
        #pragma unroll
        for (int i = 0; i < 8; i++) {
            int ch = h + i * 128;                  // 0..1023
            int reg = ch >> 9, c2 = ch & 511;
            int row = c2 >> 3, c = c2 & 7;
            const __nv_bfloat16* src = (reg ? gBL : gBH)
                + (size_t)(t * TPX + n0 + row) * CK + c * 8;
            uint32_t dst = sb + SM_B(half, buf) + reg * 8192 + row * 128 + (((c ^ (row & 7))) << 4);
            CP16(dst, (const void*)src);
        }
    };
    prefB(0, t0);
    CP_COMMIT();

    // ---- per-warp fragment addressing ----
    int m0 = (wid & 3) * 32;
    int aRow = (lane & 7) + ((lane >> 3) & 1) * 8;
    int aCh  = (lane >> 4) & 1;
    int bRow = (lane & 7) + ((lane >> 4) & 1) * 8;
    int bCh  = (lane >> 3) & 1;
    int rA0 = m0 + aRow, rA1 = rA0 + 16;
    uint32_t aH0 = sb + SM_A_H + rA0 * 128, aH1 = sb + SM_A_H + rA1 * 128;
    uint32_t aL0 = sb + SM_A_L + rA0 * 128, aL1 = sb + SM_A_L + rA1 * 128;
    int xA0 = rA0 & 7, xA1 = rA1 & 7;
    uint32_t bOff[4]; int xB[4];
    #pragma unroll
    for (int q = 0; q < 4; q++) {
        int rB = q * 16 + bRow;                    // local to half buffer
        bOff[q] = rB * 128; xB[q] = rB & 7;
    }
    int g = lane >> 2, t4 = lane & 3;
    const float K1 = 144.2695041f;                 // 100 * log2(e)

    int buf = 0;
    for (int t = t0; t < t1; t++) {
        if (t + 1 < t1) prefB(buf ^ 1, t + 1);
        CP_COMMIT();
        CP_WAIT1();
        if (t == t0) __syncthreads();              // A visibility (cross-half writers)
        else BARH(barid);

        float acc[2][8][4];
        #pragma unroll
        for (int i = 0; i < 2; i++)
            #pragma unroll
            for (int nt = 0; nt < 8; nt++)
                #pragma unroll
                for (int q = 0; q < 4; q++) acc[i][nt][q] = 0.f;

        uint32_t bB = sb + SM_B(half, buf);
        #pragma unroll
        for (int ks = 0; ks < 4; ks++) {
            uint32_t A0h[4], A1h[4], A0l[4], A1l[4], Bf[4][4];
            int chA = aCh + 2 * ks;
            LDSM4(A0h, aH0 + ((chA ^ xA0) << 4));
            LDSM4(A1h, aH1 + ((chA ^ xA1) << 4));
            LDSM4(A0l, aL0 + ((chA ^ xA0) << 4));
            LDSM4(A1l, aL1 + ((chA ^ xA1) << 4));
            int chB = bCh + 2 * ks;
            #pragma unroll
            for (int q = 0; q < 4; q++) LDSM4(Bf[q], bB + bOff[q] + ((chB ^ xB[q]) << 4));
            #pragma unroll
            for (int nt = 0; nt < 8; nt++) {
                uint32_t b0 = Bf[nt >> 1][(nt & 1) * 2];
                uint32_t b1 = Bf[nt >> 1][(nt & 1) * 2 + 1];
                MMA16816(acc[0][nt], A0h, b0, b1);          // hi*hi
                MMA16816(acc[1][nt], A1h, b0, b1);
            }
            #pragma unroll
            for (int nt = 0; nt < 8; nt++) {
                uint32_t b0 = Bf[nt >> 1][(nt & 1) * 2];
                uint32_t b1 = Bf[nt >> 1][(nt & 1) * 2 + 1];
                MMA16816(acc[0][nt], A0l, b0, b1);          // lo*hi
                MMA16816(acc[1][nt], A1l, b0, b1);
            }
            #pragma unroll
            for (int q = 0; q < 4; q++) LDSM4(Bf[q], bB + 8192 + bOff[q] + ((chB ^ xB[q]) << 4));
            #pragma unroll
            for (int nt = 0; nt < 8; nt++) {
                uint32_t b0 = Bf[nt >> 1][(nt & 1) * 2];
                uint32_t b1 = Bf[nt >> 1][(nt & 1) * 2 + 1];
                MMA16816(acc[0][nt], A0h, b0, b1);          // hi*lo
                MMA16816(acc[1][nt], A1h, b0, b1);
            }
        }

        // ---- fused softmax epilogue; direct per-warp g_part stores ----
        #pragma unroll
        for (int mt = 0; mt < 2; mt++) {
            float s0 = 0.f, u0 = 0.f, s1 = 0.f, u1 = 0.f;
            #pragma unroll
            for (int nt = 0; nt < 8; nt++) {
                float col = (float)(n0 + nt * 8 + t4 * 2);
                float e0, e1, e2, e3;
                asm("ex2.approx.ftz.f32 %0, %1;" : "=f"(e0) : "f"(fmaf(acc[mt][nt][0], K1, -K1)));
                asm("ex2.approx.ftz.f32 %0, %1;" : "=f"(e1) : "f"(fmaf(acc[mt][nt][1], K1, -K1)));
                asm("ex2.approx.ftz.f32 %0, %1;" : "=f"(e2) : "f"(fmaf(acc[mt][nt][2], K1, -K1)));
                asm("ex2.approx.ftz.f32 %0, %1;" : "=f"(e3) : "f"(fmaf(acc[mt][nt][3], K1, -K1)));
                s0 += e0 + e1;  u0 = fmaf(e0, col, u0); u0 = fmaf(e1, col + 1.f, u0);
                s1 += e2 + e3;  u1 = fmaf(e2, col, u1); u1 = fmaf(e3, col + 1.f, u1);
            }
            #pragma unroll
            for (int d = 1; d <= 2; d <<= 1) {
                s0 += __shfl_xor_sync(0xFFFFFFFF, s0, d);
                u0 += __shfl_xor_sync(0xFFFFFFFF, u0, d);
                s1 += __shfl_xor_sync(0xFFFFFFFF, s1, d);
                u1 += __shfl_xor_sync(0xFFFFFFFF, u1, d);
            }
            if (t4 == 0) {
                int r = m0 + mt * 16 + g;
                size_t row = (size_t)w * NKP + kh * 128 + r;
                float* p = g_part + (row * NTILE + t) * 4 + half * 2;
                p[0] = s0; p[1] = u0;
                float* p8 = g_part + ((row + 8) * NTILE + t) * 4 + half * 2;
                p8[0] = s1; p8[1] = u1;
            }
        }
        BARH(barid);           // half done reading buf before next prefB overwrites it
        buf ^= 1;
    }
}

// ---------------------------------------------------------------- reduce + tail merged
__global__ __launch_bounds__(256) void k_finish(const float* __restrict__ scores,
                                                float* __restrict__ out) {
    if (blockIdx.x < 192) {
        int row = blockIdx.x * 8 + (threadIdx.x >> 5);
        int lane = threadIdx.x & 31;
        const float4* p = (const float4*)(g_part + (size_t)row * NTILE * 4);
        float s = 0.f, u = 0.f, v = 0.f;
        #pragma unroll
        for (int i = 0; i < 16; i++) {
            int idx = lane + i * 32;                    // tile id
            float4 q = p[idx];
            float sp = q.x + q.z;
            float up = q.y + q.w;
            s += sp;
            u += up + 128.f * (float)(idx & 1) * sp;
            v = fmaf((float)(idx >> 1), sp, v);
        }
        #pragma unroll
        for (int d = 16; d > 0; d >>= 1) {
            s += __shfl_xor_sync(0xFFFFFFFF, s, d);
            u += __shfl_xor_sync(0xFFFFFFFF, u, d);
            v += __shfl_xor_sync(0xFFFFFFFF, v, d);
        }
        if (lane == 0) {
            float inv = 1.f / s;
            out[row * 2 + 0] = u * inv;
            out[row * 2 + 1] = v * inv;
        }
    } else {
        int w = blockIdx.x - 192, n = threadIdx.x;
        int f = (w / 3) * 4 + (w % 3) + 1;
        out[3072 + w * NKP + n] = scores[f * NKP + n];
        if (n == 0) {
            out[4608 + w] = (float)f;
            out[4614 + w] = (float)((w / 3) * 4);
        }
    }
}

extern "C" void kernel_launch(void* const* d_in, const int* in_sizes, int n_in,
                              void* d_out, int out_size) {
    (void)in_sizes; (void)n_in; (void)out_size;
    const float* scores = (const float*)d_in[0];
    const float* kd     = (const float*)d_in[1];
    const float* dd     = (const float*)d_in[2];
    float* out = (float*)d_out;

    cudaFuncSetAttribute(k_gemm, cudaFuncAttributeMaxDynamicSharedMemorySize, SM_TOT);

    k_prep_tgt<<<NGRP, 128>>>(kd);          // launch 0
    k_prep_src<<<512, 128>>>(dd, 0);        // launch 1
    k_prep_src<<<512, 128>>>(dd, 512);      // launch 2
    k_gemm<<<NCTA, 256, SM_TOT>>>();        // launch 3  (ncu lands here)
    k_finish<<<198, 256>>>(scores, out);    // launch 4
}

// round 8
// speedup vs baseline: 1.5624x; 1.0497x over previous
#include <cuda_runtime.h>
#include <cuda_bf16.h>
#include <cstdint>

// SoftmaxRefMatcher: persistent mma.sync bf16 hi/lo GEMM + fused fixed-shift softmax.
// R8: single live fragment set (reg relief), release-barrier before epilogue,
// immediate-FFMA epilogue decomposition.
// BW=8, C=64, N=256, HW=65536, WINDOW=4 -> B=2, NW=6, 12 (w,kh) groups.

#define CK     64
#define NKP    256
#define HW     65536
#define NW     6
#define TPX    128
#define NTILE  512
#define NGRP   12
#define CPG    49
#define NCTA   (NGRP * CPG)     // 588

__device__ __align__(256) __nv_bfloat16 g_Ahi[NW * NKP * CK];
__device__ __align__(256) __nv_bfloat16 g_Alo[NW * NKP * CK];
__device__ __align__(256) __nv_bfloat16 g_Bhi[2 * HW * CK];
__device__ __align__(256) __nv_bfloat16 g_Blo[2 * HW * CK];
// [row][tile][{s_half0, u_half0, s_half1, u_half1}]
__device__ __align__(256) float g_part[NW * NKP * NTILE * 4];

__device__ __forceinline__ uint32_t smem_u32(const void* p) {
    uint32_t a;
    asm("{ .reg .u64 t; cvta.to.shared.u64 t, %1; cvt.u32.u64 %0, t; }" : "=r"(a) : "l"(p));
    return a;
}
#define LDSM4(R, addr) \
    asm volatile("ldmatrix.sync.aligned.m8n8.x4.shared.b16 {%0,%1,%2,%3}, [%4];" \
        : "=r"((R)[0]), "=r"((R)[1]), "=r"((R)[2]), "=r"((R)[3]) : "r"(addr))
#define MMA16816(D, A, b0, b1) \
    asm volatile("mma.sync.aligned.m16n8k16.row.col.f32.bf16.bf16.f32 " \
        "{%0,%1,%2,%3}, {%4,%5,%6,%7}, {%8,%9}, {%0,%1,%2,%3};" \
        : "+f"((D)[0]), "+f"((D)[1]), "+f"((D)[2]), "+f"((D)[3]) \
        : "r"((A)[0]), "r"((A)[1]), "r"((A)[2]), "r"((A)[3]), "r"(b0), "r"(b1))
#define CP16(dst, src) \
    asm volatile("cp.async.cg.shared.global [%0], [%1], 16;" :: "r"(dst), "l"(src))
#define CP_COMMIT() asm volatile("cp.async.commit_group;" ::: "memory")
#define CP_WAIT1()  asm volatile("cp.async.wait_group 1;" ::: "memory")
#define BARH(id)    asm volatile("bar.sync %0, 128;" :: "r"(id) : "memory")

__device__ __forceinline__ void split_bf16(float x, __nv_bfloat16& hi, __nv_bfloat16& lo) {
    hi = __float2bfloat16(x);
    lo = __float2bfloat16(x - __bfloat162float(hi));
}

// ---------------------------------------------------------------- tgt prep
__global__ __launch_bounds__(128) void k_prep_tgt(const float* __restrict__ kd) {
    int idx = blockIdx.x;                   // 0..11
    int tid = threadIdx.x;
    int w = idx >> 1;
    int n = (idx & 1) * 128 + tid;
    int f = (w / 3) * 4 + (w % 3) + 1;
    const float* src = kd + f * CK * NKP + n;
    float v[CK]; float ss = 0.f;
    #pragma unroll
    for (int c = 0; c < CK; c++) { v[c] = src[c * NKP]; ss += v[c] * v[c]; }
    float inv = 1.f / fmaxf(sqrtf(ss), 1e-12f);
    int base = (w * NKP + n) * CK;
    #pragma unroll
    for (int c = 0; c < CK; c++) {
        __nv_bfloat16 hi, lo; split_bf16(v[c] * inv, hi, lo);
        g_Ahi[base + c] = hi; g_Alo[base + c] = lo;
    }
}

// ---------------------------------------------------------------- src prep (half grid per launch)
__global__ __launch_bounds__(128) void k_prep_src(const float* __restrict__ dd, int blk0) {
    __shared__ uint32_t sH[128 * 33], sL[128 * 33];
    int bid = blockIdx.x + blk0;
    int tid = threadIdx.x;
    int pidx = bid * 128 + tid;
    int b = pidx >> 16;
    const float* src = dd + (size_t)(b * 4) * CK * HW + (pidx & (HW - 1));
    float v[CK]; float ss = 0.f;
    #pragma unroll
    for (int c = 0; c < CK; c++) { v[c] = src[(size_t)c * HW]; ss += v[c] * v[c]; }
    float inv = 1.f / fmaxf(sqrtf(ss), 1e-12f);
    #pragma unroll
    for (int j = 0; j < 32; j++) {
        __nv_bfloat16 h0, l0, h1, l1;
        split_bf16(v[2 * j] * inv, h0, l0);
        split_bf16(v[2 * j + 1] * inv, h1, l1);
        sH[tid * 33 + j] = (uint32_t)__bfloat16_as_ushort(h0) | ((uint32_t)__bfloat16_as_ushort(h1) << 16);
        sL[tid * 33 + j] = (uint32_t)__bfloat16_as_ushort(l0) | ((uint32_t)__bfloat16_as_ushort(l1) << 16);
    }
    __syncthreads();
    uint32_t* oH = reinterpret_cast<uint32_t*>(g_Bhi) + (size_t)bid * 128 * 32;
    uint32_t* oL = reinterpret_cast<uint32_t*>(g_Blo) + (size_t)bid * 128 * 32;
    #pragma unroll
    for (int i = 0; i < 32; i++) {
        int u = tid + i * 128;
        int mm = u >> 5, j = u & 31;
        oH[u] = sH[mm * 33 + j];
        oL[u] = sL[mm * 33 + j];
    }
}

// ---------------------------------------------------------------- persistent GEMM + softmax
// smem: AH 16K | AL 16K | half0 {buf0 hi/lo 16K, buf1 16K} | half1 {32K} = 96K
#define SM_A_H 0
#define SM_A_L 16384
#define SM_B(half, buf) (32768 + (half) * 32768 + (buf) * 16384)
#define SM_TOT 98304

__global__ void __launch_bounds__(256, 2) k_gemm() {
    extern __shared__ char smem[];
    uint32_t sb = smem_u32(smem);
    int tid = threadIdx.x;
    int cta = blockIdx.x;
    int grp = cta % NGRP, j = cta / NGRP;
    int w = grp >> 1, kh = grp & 1, b = w / 3;
    int t0 = (j * NTILE) / CPG, t1 = ((j + 1) * NTILE) / CPG;

    int lane = tid & 31, wid = tid >> 5;
    int half = tid >> 7;                   // warps 0-3 -> half 0, warps 4-7 -> half 1
    int h = tid & 127;
    int n0 = half * 64;
    int barid = 1 + half;

    // ---- prefetch A (once, whole CTA) ----
    {
        const __nv_bfloat16* gAH = g_Ahi + (size_t)(w * NKP + kh * 128) * CK;
        const __nv_bfloat16* gAL = g_Alo + (size_t)(w * NKP + kh * 128) * CK;
        #pragma unroll
        for (int i = 0; i < 8; i++) {
            int ch = tid + i * 256;
            int reg = ch >> 10, c2 = ch & 1023;
            int row = c2 >> 3, c = c2 & 7;
            const __nv_bfloat16* src = (reg ? gAL : gAH) + row * CK + c * 8;
            uint32_t dst = sb + (reg ? SM_A_L : SM_A_H) + row * 128 + (((c ^ (row & 7))) << 4);
            CP16(dst, (const void*)src);
        }
    }
    const __nv_bfloat16* gBH = g_Bhi + (size_t)b * HW * CK;
    const __nv_bfloat16* gBL = g_Blo + (size_t)b * HW * CK;
    auto prefB = [&](int buf, int t) {
        #pragma unroll
        for (int i = 0; i < 8; i++) {
            int ch = h + i * 128;                  // 0..1023
            int reg = ch >> 9, c2 = ch & 511;
            int row = c2 >> 3, c = c2 & 7;
            const __nv_bfloat16* src = (reg ? gBL : gBH)
                + (size_t)(t * TPX + n0 + row) * CK + c * 8;
            uint32_t dst = sb + SM_B(half, buf) + reg * 8192 + row * 128 + (((c ^ (row & 7))) << 4);
            CP16(dst, (const void*)src);
        }
    };
    prefB(0, t0);
    CP_COMMIT();

    // ---- per-warp fragment addressing ----
    int m0 = (wid & 3) * 32;
    int aRow = (lane & 7) + ((lane >> 3) & 1) * 8;
    int aCh  = (lane >> 4) & 1;
    int bRow = (lane & 7) + ((lane >> 4) & 1) * 8;
    int bCh  = (lane >> 3) & 1;
    int rA0 = m0 + aRow, rA1 = rA0 + 16;
    uint32_t aH0 = sb + SM_A_H + rA0 * 128, aH1 = sb + SM_A_H + rA1 * 128;
    uint32_t aL0 = sb + SM_A_L + rA0 * 128, aL1 = sb + SM_A_L + rA1 * 128;
    int xA0 = rA0 & 7, xA1 = rA1 & 7;
    uint32_t bOff[4]; int xB[4];
    #pragma unroll
    for (int q = 0; q < 4; q++) {
        int rB = q * 16 + bRow;
        bOff[q] = rB * 128; xB[q] = rB & 7;
    }
    int g = lane >> 2, t4 = lane & 3;
    const float K1 = 144.2695041f;                 // 100 * log2(e)
    float t4f2 = (float)(n0 + t4 * 2);

    int buf = 0;
    for (int t = t0; t < t1; t++) {
        if (t + 1 < t1) prefB(buf ^ 1, t + 1);
        CP_COMMIT();
        CP_WAIT1();
        if (t == t0) __syncthreads();              // A + B(t0) visibility (all writers)
        else BARH(barid);                          // B(t) visibility within half

        float acc[2][8][4];
        #pragma unroll
        for (int i = 0; i < 2; i++)
            #pragma unroll
            for (int nt = 0; nt < 8; nt++)
                #pragma unroll
                for (int q = 0; q < 4; q++) acc[i][nt][q] = 0.f;

        uint32_t bB = sb + SM_B(half, buf);
        #pragma unroll
        for (int ks = 0; ks < 4; ks++) {
            uint32_t Af0[4], Af1[4], Bf[4][4];
            int chA = aCh + 2 * ks;
            int chB = bCh + 2 * ks;
            // ---- sweep 1: hi*hi ----
            LDSM4(Af0, aH0 + ((chA ^ xA0) << 4));
            LDSM4(Af1, aH1 + ((chA ^ xA1) << 4));
            #pragma unroll
            for (int q = 0; q < 4; q++) LDSM4(Bf[q], bB + bOff[q] + ((chB ^ xB[q]) << 4));
            #pragma unroll
            for (int nt = 0; nt < 8; nt++) {
                uint32_t b0 = Bf[nt >> 1][(nt & 1) * 2];
                uint32_t b1 = Bf[nt >> 1][(nt & 1) * 2 + 1];
                MMA16816(acc[0][nt], Af0, b0, b1);
                MMA16816(acc[1][nt], Af1, b0, b1);
            }
            // ---- sweep 2: lo*hi (A-lo over same regs) ----
            LDSM4(Af0, aL0 + ((chA ^ xA0) << 4));
            LDSM4(Af1, aL1 + ((chA ^ xA1) << 4));
            #pragma unroll
            for (int nt = 0; nt < 8; nt++) {
                uint32_t b0 = Bf[nt >> 1][(nt & 1) * 2];
                uint32_t b1 = Bf[nt >> 1][(nt & 1) * 2 + 1];
                MMA16816(acc[0][nt], Af0, b0, b1);
                MMA16816(acc[1][nt], Af1, b0, b1);
            }
            // ---- sweep 3: hi*lo (B-lo over B regs, A-hi reloaded) ----
            #pragma unroll
            for (int q = 0; q < 4; q++) LDSM4(Bf[q], bB + 8192 + bOff[q] + ((chB ^ xB[q]) << 4));
            LDSM4(Af0, aH0 + ((chA ^ xA0) << 4));
            LDSM4(Af1, aH1 + ((chA ^ xA1) << 4));
            #pragma unroll
            for (int nt = 0; nt < 8; nt++) {
                uint32_t b0 = Bf[nt >> 1][(nt & 1) * 2];
                uint32_t b1 = Bf[nt >> 1][(nt & 1) * 2 + 1];
                MMA16816(acc[0][nt], Af0, b0, b1);
                MMA16816(acc[1][nt], Af1, b0, b1);
            }
        }

        BARH(barid);       // release buf for overwrite (epilogue is reg-private)

        // ---- fused softmax epilogue: s = Σe, u = t4f2·s + 8·Σ(nt·p) + Σe_odd ----
        #pragma unroll
        for (int mt = 0; mt < 2; mt++) {
            float s0 = 0.f, m0f = 0.f, o0 = 0.f;
            float s1 = 0.f, m1f = 0.f, o1 = 0.f;
            #pragma unroll
            for (int nt = 0; nt < 8; nt++) {
                float ntf = (float)nt;
                float e0, e1, e2, e3;
                asm("ex2.approx.ftz.f32 %0, %1;" : "=f"(e0) : "f"(fmaf(acc[mt][nt][0], K1, -K1)));
                asm("ex2.approx.ftz.f32 %0, %1;" : "=f"(e1) : "f"(fmaf(acc[mt][nt][1], K1, -K1)));
                asm("ex2.approx.ftz.f32 %0, %1;" : "=f"(e2) : "f"(fmaf(acc[mt][nt][2], K1, -K1)));
                asm("ex2.approx.ftz.f32 %0, %1;" : "=f"(e3) : "f"(fmaf(acc[mt][nt][3], K1, -K1)));
                float p0 = e0 + e1, p1 = e2 + e3;
                s0 += p0;  m0f = fmaf(ntf, p0, m0f);  o0 += e1;
                s1 += p1;  m1f = fmaf(ntf, p1, m1f);  o1 += e3;
            }
            float u0 = fmaf(8.f, m0f, o0); u0 = fmaf(t4f2, s0, u0);
            float u1 = fmaf(8.f, m1f, o1); u1 = fmaf(t4f2, s1, u1);
            #pragma unroll
            for (int d = 1; d <= 2; d <<= 1) {
                s0 += __shfl_xor_sync(0xFFFFFFFF, s0, d);
                u0 += __shfl_xor_sync(0xFFFFFFFF, u0, d);
                s1 += __shfl_xor_sync(0xFFFFFFFF, s1, d);
                u1 += __shfl_xor_sync(0xFFFFFFFF, u1, d);
            }
            if (t4 == 0) {
                int r = m0 + mt * 16 + g;
                size_t row = (size_t)w * NKP + kh * 128 + r;
                float* p = g_part + (row * NTILE + t) * 4 + half * 2;
                p[0] = s0; p[1] = u0;
                float* p8 = g_part + ((row + 8) * NTILE + t) * 4 + half * 2;
                p8[0] = s1; p8[1] = u1;
            }
        }
        buf ^= 1;
    }
}

// ---------------------------------------------------------------- reduce + tail merged
__global__ __launch_bounds__(256) void k_finish(const float* __restrict__ scores,
                                                float* __restrict__ out) {
    if (blockIdx.x < 192) {
        int row = blockIdx.x * 8 + (threadIdx.x >> 5);
        int lane = threadIdx.x & 31;
        const float4* p = (const float4*)(g_part + (size_t)row * NTILE * 4);
        float s = 0.f, u = 0.f, v = 0.f;
        #pragma unroll
        for (int i = 0; i < 16; i++) {
            int idx = lane + i * 32;                    // tile id
            float4 q = p[idx];
            float sp = q.x + q.z;
            float up = q.y + q.w;
            s += sp;
            u += up + 128.f * (float)(idx & 1) * sp;
            v = fmaf((float)(idx >> 1), sp, v);
        }
        #pragma unroll
        for (int d = 16; d > 0; d >>= 1) {
            s += __shfl_xor_sync(0xFFFFFFFF, s, d);
            u += __shfl_xor_sync(0xFFFFFFFF, u, d);
            v += __shfl_xor_sync(0xFFFFFFFF, v, d);
        }
        if (lane == 0) {
            float inv = 1.f / s;
            out[row * 2 + 0] = u * inv;
            out[row * 2 + 1] = v * inv;
        }
    } else {
        int w = blockIdx.x - 192, n = threadIdx.x;
        int f = (w / 3) * 4 + (w % 3) + 1;
        out[3072 + w * NKP + n] = scores[f * NKP + n];
        if (n == 0) {
            out[4608 + w] = (float)f;
            out[4614 + w] = (float)((w / 3) * 4);
        }
    }
}

extern "C" void kernel_launch(void* const* d_in, const int* in_sizes, int n_in,
                              void* d_out, int out_size) {
    (void)in_sizes; (void)n_in; (void)out_size;
    const float* scores = (const float*)d_in[0];
    const float* kd     = (const float*)d_in[1];
    const float* dd     = (const float*)d_in[2];
    float* out = (float*)d_out;

    cudaFuncSetAttribute(k_gemm, cudaFuncAttributeMaxDynamicSharedMemorySize, SM_TOT);

    k_prep_tgt<<<NGRP, 128>>>(kd);          // launch 0
    k_prep_src<<<512, 128>>>(dd, 0);        // launch 1
    k_prep_src<<<512, 128>>>(dd, 512);      // launch 2
    k_gemm<<<NCTA, 256, SM_TOT>>>();        // launch 3  (ncu lands here)
    k_finish<<<198, 256>>>(scores, out);    // launch 4
}

// round 9
// speedup vs baseline: 2.1667x; 1.3867x over previous
#include <cuda_runtime.h>
#include <cuda_fp16.h>
#include <cstdint>

// SoftmaxRefMatcher: persistent mma.sync GEMM + fused fixed-shift softmax.
// R9: fp16 A-split (exact) x fp16 B (rounded) -> 2 products instead of bf16 3-product.
// BW=8, C=64, N=256, HW=65536, WINDOW=4 -> B=2, NW=6, 12 (w,kh) groups.

#define CK     64
#define NKP    256
#define HW     65536
#define NW     6
#define TPX    128
#define NTILE  512
#define NGRP   12
#define CPG    49
#define NCTA   (NGRP * CPG)     // 588

__device__ __align__(256) __half g_Ahi[NW * NKP * CK];
__device__ __align__(256) __half g_Alo[NW * NKP * CK];
__device__ __align__(256) __half g_B[2 * HW * CK];
// [row][tile][{s_half0, u_half0, s_half1, u_half1}]
__device__ __align__(256) float g_part[NW * NKP * NTILE * 4];

__device__ __forceinline__ uint32_t smem_u32(const void* p) {
    uint32_t a;
    asm("{ .reg .u64 t; cvta.to.shared.u64 t, %1; cvt.u32.u64 %0, t; }" : "=r"(a) : "l"(p));
    return a;
}
#define LDSM4(R, addr) \
    asm volatile("ldmatrix.sync.aligned.m8n8.x4.shared.b16 {%0,%1,%2,%3}, [%4];" \
        : "=r"((R)[0]), "=r"((R)[1]), "=r"((R)[2]), "=r"((R)[3]) : "r"(addr))
#define MMA16816(D, A, b0, b1) \
    asm volatile("mma.sync.aligned.m16n8k16.row.col.f32.f16.f16.f32 " \
        "{%0,%1,%2,%3}, {%4,%5,%6,%7}, {%8,%9}, {%0,%1,%2,%3};" \
        : "+f"((D)[0]), "+f"((D)[1]), "+f"((D)[2]), "+f"((D)[3]) \
        : "r"((A)[0]), "r"((A)[1]), "r"((A)[2]), "r"((A)[3]), "r"(b0), "r"(b1))
#define CP16(dst, src) \
    asm volatile("cp.async.cg.shared.global [%0], [%1], 16;" :: "r"(dst), "l"(src))
#define CP_COMMIT() asm volatile("cp.async.commit_group;" ::: "memory")
#define CP_WAIT1()  asm volatile("cp.async.wait_group 1;" ::: "memory")
#define BARH(id)    asm volatile("bar.sync %0, 128;" :: "r"(id) : "memory")

__device__ __forceinline__ void split_f16(float x, __half& hi, __half& lo) {
    hi = __float2half(x);
    lo = __float2half(x - __half2float(hi));
}

// ---------------------------------------------------------------- tgt prep (A: exact fp16 split)
__global__ __launch_bounds__(128) void k_prep_tgt(const float* __restrict__ kd) {
    int idx = blockIdx.x;                   // 0..11
    int tid = threadIdx.x;
    int w = idx >> 1;
    int n = (idx & 1) * 128 + tid;
    int f = (w / 3) * 4 + (w % 3) + 1;
    const float* src = kd + f * CK * NKP + n;
    float v[CK]; float ss = 0.f;
    #pragma unroll
    for (int c = 0; c < CK; c++) { v[c] = src[c * NKP]; ss += v[c] * v[c]; }
    float inv = 1.f / fmaxf(sqrtf(ss), 1e-12f);
    int base = (w * NKP + n) * CK;
    #pragma unroll
    for (int c = 0; c < CK; c++) {
        __half hi, lo; split_f16(v[c] * inv, hi, lo);
        g_Ahi[base + c] = hi; g_Alo[base + c] = lo;
    }
}

// ---------------------------------------------------------------- src prep (B: single fp16, transposed)
__global__ __launch_bounds__(128) void k_prep_src(const float* __restrict__ dd, int blk0) {
    __shared__ uint32_t sH[128 * 33];
    int bid = blockIdx.x + blk0;
    int tid = threadIdx.x;
    int pidx = bid * 128 + tid;
    int b = pidx >> 16;
    const float* src = dd + (size_t)(b * 4) * CK * HW + (pidx & (HW - 1));
    float v[CK]; float ss = 0.f;
    #pragma unroll
    for (int c = 0; c < CK; c++) { v[c] = src[(size_t)c * HW]; ss += v[c] * v[c]; }
    float inv = 1.f / fmaxf(sqrtf(ss), 1e-12f);
    #pragma unroll
    for (int j = 0; j < 32; j++) {
        __half h0 = __float2half(v[2 * j] * inv);
        __half h1 = __float2half(v[2 * j + 1] * inv);
        sH[tid * 33 + j] = (uint32_t)__half_as_ushort(h0) | ((uint32_t)__half_as_ushort(h1) << 16);
    }
    __syncthreads();
    uint32_t* oH = reinterpret_cast<uint32_t*>(g_B) + (size_t)bid * 128 * 32;
    #pragma unroll
    for (int i = 0; i < 32; i++) {
        int u = tid + i * 128;
        int mm = u >> 5, j = u & 31;
        oH[u] = sH[mm * 33 + j];
    }
}

// ---------------------------------------------------------------- persistent GEMM + softmax
// smem: AH 16K | AL 16K | half0 {buf0 8K, buf1 8K} | half1 {16K} = 64K
#define SM_A_H 0
#define SM_A_L 16384
#define SM_B(half, buf) (32768 + (half) * 16384 + (buf) * 8192)
#define SM_TOT 65536

__global__ void __launch_bounds__(256, 2) k_gemm() {
    extern __shared__ char smem[];
    uint32_t sb = smem_u32(smem);
    int tid = threadIdx.x;
    int cta = blockIdx.x;
    int grp = cta % NGRP, j = cta / NGRP;
    int w = grp >> 1, kh = grp & 1, b = w / 3;
    int t0 = (j * NTILE) / CPG, t1 = ((j + 1) * NTILE) / CPG;

    int lane = tid & 31, wid = tid >> 5;
    int half = tid >> 7;                   // warps 0-3 -> half 0, warps 4-7 -> half 1
    int h = tid & 127;
    int n0 = half * 64;
    int barid = 1 + half;

    // ---- prefetch A (once, whole CTA): hi+lo = 32KB, 8 chunks/thread ----
    {
        const __half* gAH = g_Ahi + (size_t)(w * NKP + kh * 128) * CK;
        const __half* gAL = g_Alo + (size_t)(w * NKP + kh * 128) * CK;
        #pragma unroll
        for (int i = 0; i < 8; i++) {
            int ch = tid + i * 256;
            int reg = ch >> 10, c2 = ch & 1023;
            int row = c2 >> 3, c = c2 & 7;
            const __half* src = (reg ? gAL : gAH) + row * CK + c * 8;
            uint32_t dst = sb + (reg ? SM_A_L : SM_A_H) + row * 128 + (((c ^ (row & 7))) << 4);
            CP16(dst, (const void*)src);
        }
    }
    const __half* gB = g_B + (size_t)b * HW * CK;
    // per-half B prefetch: 64 px rows = 8KB by 128 threads, 4 chunks each
    auto prefB = [&](int buf, int t) {
        #pragma unroll
        for (int i = 0; i < 4; i++) {
            int ch = h + i * 128;                  // 0..511
            int row = ch >> 3, c = ch & 7;
            const __half* src = gB + (size_t)(t * TPX + n0 + row) * CK + c * 8;
            uint32_t dst = sb + SM_B(half, buf) + row * 128 + (((c ^ (row & 7))) << 4);
            CP16(dst, (const void*)src);
        }
    };
    prefB(0, t0);
    CP_COMMIT();

    // ---- per-warp fragment addressing ----
    int m0 = (wid & 3) * 32;
    int aRow = (lane & 7) + ((lane >> 3) & 1) * 8;
    int aCh  = (lane >> 4) & 1;
    int bRow = (lane & 7) + ((lane >> 4) & 1) * 8;
    int bCh  = (lane >> 3) & 1;
    int rA0 = m0 + aRow, rA1 = rA0 + 16;
    uint32_t aH0 = sb + SM_A_H + rA0 * 128, aH1 = sb + SM_A_H + rA1 * 128;
    uint32_t aL0 = sb + SM_A_L + rA0 * 128, aL1 = sb + SM_A_L + rA1 * 128;
    int xA0 = rA0 & 7, xA1 = rA1 & 7;
    uint32_t bOff[4]; int xB[4];
    #pragma unroll
    for (int q = 0; q < 4; q++) {
        int rB = q * 16 + bRow;
        bOff[q] = rB * 128; xB[q] = rB & 7;
    }
    int g = lane >> 2, t4 = lane & 3;
    const float K1 = 144.2695041f;                 // 100 * log2(e)
    float t4f2 = (float)(n0 + t4 * 2);

    int buf = 0;
    for (int t = t0; t < t1; t++) {
        if (t + 1 < t1) prefB(buf ^ 1, t + 1);
        CP_COMMIT();
        CP_WAIT1();
        if (t == t0) __syncthreads();              // A + B(t0) visibility (all writers)
        else BARH(barid);                          // B(t) visibility within half

        float acc[2][8][4];
        #pragma unroll
        for (int i = 0; i < 2; i++)
            #pragma unroll
            for (int nt = 0; nt < 8; nt++)
                #pragma unroll
                for (int q = 0; q < 4; q++) acc[i][nt][q] = 0.f;

        uint32_t bB = sb + SM_B(half, buf);
        #pragma unroll
        for (int ks = 0; ks < 4; ks++) {
            uint32_t Af0[4], Af1[4], Bf[4][4];
            int chA = aCh + 2 * ks;
            int chB = bCh + 2 * ks;
            // ---- sweep 1: a_hi * b ----
            LDSM4(Af0, aH0 + ((chA ^ xA0) << 4));
            LDSM4(Af1, aH1 + ((chA ^ xA1) << 4));
            #pragma unroll
            for (int q = 0; q < 4; q++) LDSM4(Bf[q], bB + bOff[q] + ((chB ^ xB[q]) << 4));
            #pragma unroll
            for (int nt = 0; nt < 8; nt++) {
                uint32_t b0 = Bf[nt >> 1][(nt & 1) * 2];
                uint32_t b1 = Bf[nt >> 1][(nt & 1) * 2 + 1];
                MMA16816(acc[0][nt], Af0, b0, b1);
                MMA16816(acc[1][nt], Af1, b0, b1);
            }
            // ---- sweep 2: a_lo * b (A-lo over same regs) ----
            LDSM4(Af0, aL0 + ((chA ^ xA0) << 4));
            LDSM4(Af1, aL1 + ((chA ^ xA1) << 4));
            #pragma unroll
            for (int nt = 0; nt < 8; nt++) {
                uint32_t b0 = Bf[nt >> 1][(nt & 1) * 2];
                uint32_t b1 = Bf[nt >> 1][(nt & 1) * 2 + 1];
                MMA16816(acc[0][nt], Af0, b0, b1);
                MMA16816(acc[1][nt], Af1, b0, b1);
            }
        }

        BARH(barid);       // release buf for overwrite (epilogue is reg-private)

        // ---- fused softmax epilogue: s = Σe, u = t4f2·s + 8·Σ(nt·p) + Σe_odd ----
        #pragma unroll
        for (int mt = 0; mt < 2; mt++) {
            float s0 = 0.f, m0f = 0.f, o0 = 0.f;
            float s1 = 0.f, m1f = 0.f, o1 = 0.f;
            #pragma unroll
            for (int nt = 0; nt < 8; nt++) {
                float ntf = (float)nt;
                float e0, e1, e2, e3;
                asm("ex2.approx.ftz.f32 %0, %1;" : "=f"(e0) : "f"(fmaf(acc[mt][nt][0], K1, -K1)));
                asm("ex2.approx.ftz.f32 %0, %1;" : "=f"(e1) : "f"(fmaf(acc[mt][nt][1], K1, -K1)));
                asm("ex2.approx.ftz.f32 %0, %1;" : "=f"(e2) : "f"(fmaf(acc[mt][nt][2], K1, -K1)));
                asm("ex2.approx.ftz.f32 %0, %1;" : "=f"(e3) : "f"(fmaf(acc[mt][nt][3], K1, -K1)));
                float p0 = e0 + e1, p1 = e2 + e3;
                s0 += p0;  m0f = fmaf(ntf, p0, m0f);  o0 += e1;
                s1 += p1;  m1f = fmaf(ntf, p1, m1f);  o1 += e3;
            }
            float u0 = fmaf(8.f, m0f, o0); u0 = fmaf(t4f2, s0, u0);
            float u1 = fmaf(8.f, m1f, o1); u1 = fmaf(t4f2, s1, u1);
            #pragma unroll
            for (int d = 1; d <= 2; d <<= 1) {
                s0 += __shfl_xor_sync(0xFFFFFFFF, s0, d);
                u0 += __shfl_xor_sync(0xFFFFFFFF, u0, d);
                s1 += __shfl_xor_sync(0xFFFFFFFF, s1, d);
                u1 += __shfl_xor_sync(0xFFFFFFFF, u1, d);
            }
            if (t4 == 0) {
                int r = m0 + mt * 16 + g;
                size_t row = (size_t)w * NKP + kh * 128 + r;
                float* p = g_part + (row * NTILE + t) * 4 + half * 2;
                p[0] = s0; p[1] = u0;
                float* p8 = g_part + ((row + 8) * NTILE + t) * 4 + half * 2;
                p8[0] = s1; p8[1] = u1;
            }
        }
        buf ^= 1;
    }
}

// ---------------------------------------------------------------- reduce + tail merged
__global__ __launch_bounds__(256) void k_finish(const float* __restrict__ scores,
                                                float* __restrict__ out) {
    if (blockIdx.x < 192) {
        int row = blockIdx.x * 8 + (threadIdx.x >> 5);
        int lane = threadIdx.x & 31;
        const float4* p = (const float4*)(g_part + (size_t)row * NTILE * 4);
        float s = 0.f, u = 0.f, v = 0.f;
        #pragma unroll
        for (int i = 0; i < 16; i++) {
            int idx = lane + i * 32;                    // tile id
            float4 q = p[idx];
            float sp = q.x + q.z;
            float up = q.y + q.w;
            s += sp;
            u += up + 128.f * (float)(idx & 1) * sp;
            v = fmaf((float)(idx >> 1), sp, v);
        }
        #pragma unroll
        for (int d = 16; d > 0; d >>= 1) {
            s += __shfl_xor_sync(0xFFFFFFFF, s, d);
            u += __shfl_xor_sync(0xFFFFFFFF, u, d);
            v += __shfl_xor_sync(0xFFFFFFFF, v, d);
        }
        if (lane == 0) {
            float inv = 1.f / s;
            out[row * 2 + 0] = u * inv;
            out[row * 2 + 1] = v * inv;
        }
    } else {
        int w = blockIdx.x - 192, n = threadIdx.x;
        int f = (w / 3) * 4 + (w % 3) + 1;
        out[3072 + w * NKP + n] = scores[f * NKP + n];
        if (n == 0) {
            out[4608 + w] = (float)f;
            out[4614 + w] = (float)((w / 3) * 4);
        }
    }
}

extern "C" void kernel_launch(void* const* d_in, const int* in_sizes, int n_in,
                              void* d_out, int out_size) {
    (void)in_sizes; (void)n_in; (void)out_size;
    const float* scores = (const float*)d_in[0];
    const float* kd     = (const float*)d_in[1];
    const float* dd     = (const float*)d_in[2];
    float* out = (float*)d_out;

    cudaFuncSetAttribute(k_gemm, cudaFuncAttributeMaxDynamicSharedMemorySize, SM_TOT);

    k_prep_tgt<<<NGRP, 128>>>(kd);          // launch 0
    k_prep_src<<<512, 128>>>(dd, 0);        // launch 1
    k_prep_src<<<512, 128>>>(dd, 512);      // launch 2
    k_gemm<<<NCTA, 256, SM_TOT>>>();        // launch 3  (ncu lands here)
    k_finish<<<198, 256>>>(scores, out);    // launch 4
}

// round 10
// speedup vs baseline: 2.2128x; 1.0213x over previous
#include <cuda_runtime.h>
#include <cuda_fp16.h>
#include <cstdint>

// SoftmaxRefMatcher: persistent mma.sync fp16-split GEMM + fused fixed-shift softmax.
// R10: cross-tile register accumulation of (s,u,v) — one shuffle+store per CTA
// instead of per tile; g_part 25MB -> 2.4MB.
// BW=8, C=64, N=256, HW=65536, WINDOW=4 -> B=2, NW=6, 12 (w,kh) groups.

#define CK     64
#define NKP    256
#define HW     65536
#define NW     6
#define TPX    128
#define NTILE  512
#define NGRP   12
#define CPG    49
#define NCTA   (NGRP * CPG)     // 588
#define NPART  (CPG * 2)        // partials per row: 49 CTAs x 2 halves

__device__ __align__(256) __half g_Ahi[NW * NKP * CK];
__device__ __align__(256) __half g_Alo[NW * NKP * CK];
__device__ __align__(256) __half g_B[2 * HW * CK];
__device__ __align__(256) float4 g_part[NW * NKP * NPART];   // {s,u,v,pad}

__device__ __forceinline__ uint32_t smem_u32(const void* p) {
    uint32_t a;
    asm("{ .reg .u64 t; cvta.to.shared.u64 t, %1; cvt.u32.u64 %0, t; }" : "=r"(a) : "l"(p));
    return a;
}
#define LDSM4(R, addr) \
    asm volatile("ldmatrix.sync.aligned.m8n8.x4.shared.b16 {%0,%1,%2,%3}, [%4];" \
        : "=r"((R)[0]), "=r"((R)[1]), "=r"((R)[2]), "=r"((R)[3]) : "r"(addr))
#define MMA16816(D, A, b0, b1) \
    asm volatile("mma.sync.aligned.m16n8k16.row.col.f32.f16.f16.f32 " \
        "{%0,%1,%2,%3}, {%4,%5,%6,%7}, {%8,%9}, {%0,%1,%2,%3};" \
        : "+f"((D)[0]), "+f"((D)[1]), "+f"((D)[2]), "+f"((D)[3]) \
        : "r"((A)[0]), "r"((A)[1]), "r"((A)[2]), "r"((A)[3]), "r"(b0), "r"(b1))
#define CP16(dst, src) \
    asm volatile("cp.async.cg.shared.global [%0], [%1], 16;" :: "r"(dst), "l"(src))
#define CP_COMMIT() asm volatile("cp.async.commit_group;" ::: "memory")
#define CP_WAIT1()  asm volatile("cp.async.wait_group 1;" ::: "memory")
#define BARH(id)    asm volatile("bar.sync %0, 128;" :: "r"(id) : "memory")

__device__ __forceinline__ void split_f16(float x, __half& hi, __half& lo) {
    hi = __float2half(x);
    lo = __float2half(x - __half2float(hi));
}

// ---------------------------------------------------------------- tgt prep (A: exact fp16 split)
__global__ __launch_bounds__(128) void k_prep_tgt(const float* __restrict__ kd) {
    int idx = blockIdx.x;                   // 0..11
    int tid = threadIdx.x;
    int w = idx >> 1;
    int n = (idx & 1) * 128 + tid;
    int f = (w / 3) * 4 + (w % 3) + 1;
    const float* src = kd + f * CK * NKP + n;
    float v[CK]; float ss = 0.f;
    #pragma unroll
    for (int c = 0; c < CK; c++) { v[c] = src[c * NKP]; ss += v[c] * v[c]; }
    float inv = 1.f / fmaxf(sqrtf(ss), 1e-12f);
    int base = (w * NKP + n) * CK;
    #pragma unroll
    for (int c = 0; c < CK; c++) {
        __half hi, lo; split_f16(v[c] * inv, hi, lo);
        g_Ahi[base + c] = hi; g_Alo[base + c] = lo;
    }
}

// ---------------------------------------------------------------- src prep (B: fp16, transposed)
__global__ __launch_bounds__(128) void k_prep_src(const float* __restrict__ dd, int blk0) {
    __shared__ uint32_t sH[128 * 33];
    int bid = blockIdx.x + blk0;
    int tid = threadIdx.x;
    int pidx = bid * 128 + tid;
    int b = pidx >> 16;
    const float* src = dd + (size_t)(b * 4) * CK * HW + (pidx & (HW - 1));
    float v[CK]; float ss = 0.f;
    #pragma unroll
    for (int c = 0; c < CK; c++) { v[c] = src[(size_t)c * HW]; ss += v[c] * v[c]; }
    float inv = 1.f / fmaxf(sqrtf(ss), 1e-12f);
    #pragma unroll
    for (int j = 0; j < 32; j++) {
        __half h0 = __float2half(v[2 * j] * inv);
        __half h1 = __float2half(v[2 * j + 1] * inv);
        sH[tid * 33 + j] = (uint32_t)__half_as_ushort(h0) | ((uint32_t)__half_as_ushort(h1) << 16);
    }
    __syncthreads();
    uint32_t* oH = reinterpret_cast<uint32_t*>(g_B) + (size_t)bid * 128 * 32;
    #pragma unroll
    for (int i = 0; i < 32; i++) {
        int u = tid + i * 128;
        int mm = u >> 5, j = u & 31;
        oH[u] = sH[mm * 33 + j];
    }
}

// ---------------------------------------------------------------- persistent GEMM + softmax
// smem: AH 16K | AL 16K | half0 {buf0 8K, buf1 8K} | half1 {16K} = 64K
#define SM_A_H 0
#define SM_A_L 16384
#define SM_B(half, buf) (32768 + (half) * 16384 + (buf) * 8192)
#define SM_TOT 65536

__global__ void __launch_bounds__(256, 2) k_gemm() {
    extern __shared__ char smem[];
    uint32_t sb = smem_u32(smem);
    int tid = threadIdx.x;
    int cta = blockIdx.x;
    int grp = cta % NGRP, j = cta / NGRP;
    int w = grp >> 1, kh = grp & 1, b = w / 3;
    int t0 = (j * NTILE) / CPG, t1 = ((j + 1) * NTILE) / CPG;

    int lane = tid & 31, wid = tid >> 5;
    int half = tid >> 7;                   // warps 0-3 -> half 0, warps 4-7 -> half 1
    int h = tid & 127;
    int n0 = half * 64;
    int barid = 1 + half;

    // ---- prefetch A (once, whole CTA) ----
    {
        const __half* gAH = g_Ahi + (size_t)(w * NKP + kh * 128) * CK;
        const __half* gAL = g_Alo + (size_t)(w * NKP + kh * 128) * CK;
        #pragma unroll
        for (int i = 0; i < 8; i++) {
            int ch = tid + i * 256;
            int reg = ch >> 10, c2 = ch & 1023;
            int row = c2 >> 3, c = c2 & 7;
            const __half* src = (reg ? gAL : gAH) + row * CK + c * 8;
            uint32_t dst = sb + (reg ? SM_A_L : SM_A_H) + row * 128 + (((c ^ (row & 7))) << 4);
            CP16(dst, (const void*)src);
        }
    }
    const __half* gB = g_B + (size_t)b * HW * CK;
    auto prefB = [&](int buf, int t) {
        #pragma unroll
        for (int i = 0; i < 4; i++) {
            int ch = h + i * 128;                  // 0..511
            int row = ch >> 3, c = ch & 7;
            const __half* src = gB + (size_t)(t * TPX + n0 + row) * CK + c * 8;
            uint32_t dst = sb + SM_B(half, buf) + row * 128 + (((c ^ (row & 7))) << 4);
            CP16(dst, (const void*)src);
        }
    };
    prefB(0, t0);
    CP_COMMIT();

    // ---- per-warp fragment addressing ----
    int m0 = (wid & 3) * 32;
    int aRow = (lane & 7) + ((lane >> 3) & 1) * 8;
    int aCh  = (lane >> 4) & 1;
    int bRow = (lane & 7) + ((lane >> 4) & 1) * 8;
    int bCh  = (lane >> 3) & 1;
    int rA0 = m0 + aRow, rA1 = rA0 + 16;
    uint32_t aH0 = sb + SM_A_H + rA0 * 128, aH1 = sb + SM_A_H + rA1 * 128;
    uint32_t aL0 = sb + SM_A_L + rA0 * 128, aL1 = sb + SM_A_L + rA1 * 128;
    int xA0 = rA0 & 7, xA1 = rA1 & 7;
    uint32_t bOff[4]; int xB[4];
    #pragma unroll
    for (int q = 0; q < 4; q++) {
        int rB = q * 16 + bRow;
        bOff[q] = rB * 128; xB[q] = rB & 7;
    }
    int g = lane >> 2, t4 = lane & 3;
    const float K1 = 144.2695041f;                 // 100 * log2(e)
    float t4f2 = (float)(n0 + t4 * 2);

    // cross-tile accumulators: [mt][subrow] for rows m0+mt*16+g (+8)
    float sA[2][2] = {{0.f,0.f},{0.f,0.f}};
    float uA[2][2] = {{0.f,0.f},{0.f,0.f}};
    float vA[2][2] = {{0.f,0.f},{0.f,0.f}};

    int buf = 0;
    for (int t = t0; t < t1; t++) {
        if (t + 1 < t1) prefB(buf ^ 1, t + 1);
        CP_COMMIT();
        CP_WAIT1();
        if (t == t0) __syncthreads();              // A + B(t0) visibility
        else BARH(barid);                          // B(t) visibility within half

        float acc[2][8][4];
        #pragma unroll
        for (int i = 0; i < 2; i++)
            #pragma unroll
            for (int nt = 0; nt < 8; nt++)
                #pragma unroll
                for (int q = 0; q < 4; q++) acc[i][nt][q] = 0.f;

        uint32_t bB = sb + SM_B(half, buf);
        #pragma unroll
        for (int ks = 0; ks < 4; ks++) {
            uint32_t Af0[4], Af1[4], Bf[4][4];
            int chA = aCh + 2 * ks;
            int chB = bCh + 2 * ks;
            // sweep 1: a_hi * b
            LDSM4(Af0, aH0 + ((chA ^ xA0) << 4));
            LDSM4(Af1, aH1 + ((chA ^ xA1) << 4));
            #pragma unroll
            for (int q = 0; q < 4; q++) LDSM4(Bf[q], bB + bOff[q] + ((chB ^ xB[q]) << 4));
            #pragma unroll
            for (int nt = 0; nt < 8; nt++) {
                uint32_t b0 = Bf[nt >> 1][(nt & 1) * 2];
                uint32_t b1 = Bf[nt >> 1][(nt & 1) * 2 + 1];
                MMA16816(acc[0][nt], Af0, b0, b1);
                MMA16816(acc[1][nt], Af1, b0, b1);
            }
            // sweep 2: a_lo * b
            LDSM4(Af0, aL0 + ((chA ^ xA0) << 4));
            LDSM4(Af1, aL1 + ((chA ^ xA1) << 4));
            #pragma unroll
            for (int nt = 0; nt < 8; nt++) {
                uint32_t b0 = Bf[nt >> 1][(nt & 1) * 2];
                uint32_t b1 = Bf[nt >> 1][(nt & 1) * 2 + 1];
                MMA16816(acc[0][nt], Af0, b0, b1);
                MMA16816(acc[1][nt], Af1, b0, b1);
            }
        }

        BARH(barid);       // release buf (epilogue is reg-private)

        // ---- epilogue: per-tile (s,u) then fold into cross-tile accumulators ----
        float uoff = (float)((t & 1) * 128);       // global-u tile offset
        float vt = (float)(t >> 1);                // v constant for this tile
        #pragma unroll
        for (int mt = 0; mt < 2; mt++) {
            float s0 = 0.f, m0f = 0.f, o0 = 0.f;
            float s1 = 0.f, m1f = 0.f, o1 = 0.f;
            #pragma unroll
            for (int nt = 0; nt < 8; nt++) {
                float ntf = (float)nt;
                float e0, e1, e2, e3;
                asm("ex2.approx.ftz.f32 %0, %1;" : "=f"(e0) : "f"(fmaf(acc[mt][nt][0], K1, -K1)));
                asm("ex2.approx.ftz.f32 %0, %1;" : "=f"(e1) : "f"(fmaf(acc[mt][nt][1], K1, -K1)));
                asm("ex2.approx.ftz.f32 %0, %1;" : "=f"(e2) : "f"(fmaf(acc[mt][nt][2], K1, -K1)));
                asm("ex2.approx.ftz.f32 %0, %1;" : "=f"(e3) : "f"(fmaf(acc[mt][nt][3], K1, -K1)));
                float p0 = e0 + e1, p1 = e2 + e3;
                s0 += p0;  m0f = fmaf(ntf, p0, m0f);  o0 += e1;
                s1 += p1;  m1f = fmaf(ntf, p1, m1f);  o1 += e3;
            }
            float u0 = fmaf(8.f, m0f, o0); u0 = fmaf(t4f2 + uoff, s0, u0);
            float u1 = fmaf(8.f, m1f, o1); u1 = fmaf(t4f2 + uoff, s1, u1);
            sA[mt][0] += s0;  uA[mt][0] += u0;  vA[mt][0] = fmaf(vt, s0, vA[mt][0]);
            sA[mt][1] += s1;  uA[mt][1] += u1;  vA[mt][1] = fmaf(vt, s1, vA[mt][1]);
        }
        buf ^= 1;
    }

    // ---- single final reduce across the 4 t4-lanes + store ----
    #pragma unroll
    for (int mt = 0; mt < 2; mt++) {
        #pragma unroll
        for (int sr = 0; sr < 2; sr++) {
            float s = sA[mt][sr], u = uA[mt][sr], v = vA[mt][sr];
            #pragma unroll
            for (int d = 1; d <= 2; d <<= 1) {
                s += __shfl_xor_sync(0xFFFFFFFF, s, d);
                u += __shfl_xor_sync(0xFFFFFFFF, u, d);
                v += __shfl_xor_sync(0xFFFFFFFF, v, d);
            }
            if (t4 == 0) {
                int r = m0 + mt * 16 + sr * 8 + g;
                size_t row = (size_t)w * NKP + kh * 128 + r;
                g_part[row * NPART + j * 2 + half] = make_float4(s, u, v, 0.f);
            }
        }
    }
}

// ---------------------------------------------------------------- reduce + tail merged
__global__ __launch_bounds__(256) void k_finish(const float* __restrict__ scores,
                                                float* __restrict__ out) {
    if (blockIdx.x < 192) {
        int row = blockIdx.x * 8 + (threadIdx.x >> 5);
        int lane = threadIdx.x & 31;
        const float4* p = g_part + (size_t)row * NPART;
        float s = 0.f, u = 0.f, v = 0.f;
        #pragma unroll
        for (int i = 0; i < 4; i++) {
            int idx = lane + i * 32;
            if (idx < NPART) {
                float4 q = p[idx];
                s += q.x; u += q.y; v += q.z;
            }
        }
        #pragma unroll
        for (int d = 16; d > 0; d >>= 1) {
            s += __shfl_xor_sync(0xFFFFFFFF, s, d);
            u += __shfl_xor_sync(0xFFFFFFFF, u, d);
            v += __shfl_xor_sync(0xFFFFFFFF, v, d);
        }
        if (lane == 0) {
            float inv = 1.f / s;
            out[row * 2 + 0] = u * inv;
            out[row * 2 + 1] = v * inv;
        }
    } else {
        int w = blockIdx.x - 192, n = threadIdx.x;
        int f = (w / 3) * 4 + (w % 3) + 1;
        out[3072 + w * NKP + n] = scores[f * NKP + n];
        if (n == 0) {
            out[4608 + w] = (float)f;
            out[4614 + w] = (float)((w / 3) * 4);
        }
    }
}

extern "C" void kernel_launch(void* const* d_in, const int* in_sizes, int n_in,
                              void* d_out, int out_size) {
    (void)in_sizes; (void)n_in; (void)out_size;
    const float* scores = (const float*)d_in[0];
    const float* kd     = (const float*)d_in[1];
    const float* dd     = (const float*)d_in[2];
    float* out = (float*)d_out;

    cudaFuncSetAttribute(k_gemm, cudaFuncAttributeMaxDynamicSharedMemorySize, SM_TOT);

    k_prep_tgt<<<NGRP, 128>>>(kd);          // launch 0
    k_prep_src<<<512, 128>>>(dd, 0);        // launch 1
    k_prep_src<<<512, 128>>>(dd, 512);      // launch 2
    k_gemm<<<NCTA, 256, SM_TOT>>>();        // launch 3  (ncu lands here)
    k_finish<<<198, 256>>>(scores, out);    // launch 4
}

// round 11
// speedup vs baseline: 3.0507x; 1.3787x over previous
#include <cuda_runtime.h>
#include <cuda_fp16.h>
#include <cstdint>

// SoftmaxRefMatcher: persistent mma.sync fp16 GEMM + fused fixed-shift softmax.
// R11: single fp16 product (a_lo dropped). Error budget: A-rounding adds an
// independent term equal to B's -> rel_err ~7e-4 (< 1e-3).
// BW=8, C=64, N=256, HW=65536, WINDOW=4 -> B=2, NW=6, 12 (w,kh) groups.

#define CK     64
#define NKP    256
#define HW     65536
#define NW     6
#define TPX    128
#define NTILE  512
#define NGRP   12
#define CPG    49
#define NCTA   (NGRP * CPG)     // 588
#define NPART  (CPG * 2)        // partials per row: 49 CTAs x 2 halves

__device__ __align__(256) __half g_A[NW * NKP * CK];
__device__ __align__(256) __half g_B[2 * HW * CK];
__device__ __align__(256) float4 g_part[NW * NKP * NPART];   // {s,u,v,pad}

__device__ __forceinline__ uint32_t smem_u32(const void* p) {
    uint32_t a;
    asm("{ .reg .u64 t; cvta.to.shared.u64 t, %1; cvt.u32.u64 %0, t; }" : "=r"(a) : "l"(p));
    return a;
}
#define LDSM4(R, addr) \
    asm volatile("ldmatrix.sync.aligned.m8n8.x4.shared.b16 {%0,%1,%2,%3}, [%4];" \
        : "=r"((R)[0]), "=r"((R)[1]), "=r"((R)[2]), "=r"((R)[3]) : "r"(addr))
#define MMA16816(D, A, b0, b1) \
    asm volatile("mma.sync.aligned.m16n8k16.row.col.f32.f16.f16.f32 " \
        "{%0,%1,%2,%3}, {%4,%5,%6,%7}, {%8,%9}, {%0,%1,%2,%3};" \
        : "+f"((D)[0]), "+f"((D)[1]), "+f"((D)[2]), "+f"((D)[3]) \
        : "r"((A)[0]), "r"((A)[1]), "r"((A)[2]), "r"((A)[3]), "r"(b0), "r"(b1))
#define CP16(dst, src) \
    asm volatile("cp.async.cg.shared.global [%0], [%1], 16;" :: "r"(dst), "l"(src))
#define CP_COMMIT() asm volatile("cp.async.commit_group;" ::: "memory")
#define CP_WAIT1()  asm volatile("cp.async.wait_group 1;" ::: "memory")
#define BARH(id)    asm volatile("bar.sync %0, 128;" :: "r"(id) : "memory")

// ---------------------------------------------------------------- tgt prep (A: fp16)
__global__ __launch_bounds__(128) void k_prep_tgt(const float* __restrict__ kd) {
    int idx = blockIdx.x;                   // 0..11
    int tid = threadIdx.x;
    int w = idx >> 1;
    int n = (idx & 1) * 128 + tid;
    int f = (w / 3) * 4 + (w % 3) + 1;
    const float* src = kd + f * CK * NKP + n;
    float v[CK]; float ss = 0.f;
    #pragma unroll
    for (int c = 0; c < CK; c++) { v[c] = src[c * NKP]; ss += v[c] * v[c]; }
    float inv = 1.f / fmaxf(sqrtf(ss), 1e-12f);
    int base = (w * NKP + n) * CK;
    #pragma unroll
    for (int c = 0; c < CK; c++) g_A[base + c] = __float2half(v[c] * inv);
}

// ---------------------------------------------------------------- src prep (B: fp16, transposed)
__global__ __launch_bounds__(128) void k_prep_src(const float* __restrict__ dd, int blk0) {
    __shared__ uint32_t sH[128 * 33];
    int bid = blockIdx.x + blk0;
    int tid = threadIdx.x;
    int pidx = bid * 128 + tid;
    int b = pidx >> 16;
    const float* src = dd + (size_t)(b * 4) * CK * HW + (pidx & (HW - 1));
    float v[CK]; float ss = 0.f;
    #pragma unroll
    for (int c = 0; c < CK; c++) { v[c] = src[(size_t)c * HW]; ss += v[c] * v[c]; }
    float inv = 1.f / fmaxf(sqrtf(ss), 1e-12f);
    #pragma unroll
    for (int j = 0; j < 32; j++) {
        __half h0 = __float2half(v[2 * j] * inv);
        __half h1 = __float2half(v[2 * j + 1] * inv);
        sH[tid * 33 + j] = (uint32_t)__half_as_ushort(h0) | ((uint32_t)__half_as_ushort(h1) << 16);
    }
    __syncthreads();
    uint32_t* oH = reinterpret_cast<uint32_t*>(g_B) + (size_t)bid * 128 * 32;
    #pragma unroll
    for (int i = 0; i < 32; i++) {
        int u = tid + i * 128;
        int mm = u >> 5, j = u & 31;
        oH[u] = sH[mm * 33 + j];
    }
}

// ---------------------------------------------------------------- persistent GEMM + softmax
// smem: A 16K | half0 {buf0 8K, buf1 8K} | half1 {16K} = 48K
#define SM_A 0
#define SM_B(half, buf) (16384 + (half) * 16384 + (buf) * 8192)
#define SM_TOT 49152

__global__ void __launch_bounds__(256, 2) k_gemm() {
    extern __shared__ char smem[];
    uint32_t sb = smem_u32(smem);
    int tid = threadIdx.x;
    int cta = blockIdx.x;
    int grp = cta % NGRP, j = cta / NGRP;
    int w = grp >> 1, kh = grp & 1, b = w / 3;
    int t0 = (j * NTILE) / CPG, t1 = ((j + 1) * NTILE) / CPG;

    int lane = tid & 31, wid = tid >> 5;
    int half = tid >> 7;                   // warps 0-3 -> half 0, warps 4-7 -> half 1
    int h = tid & 127;
    int n0 = half * 64;
    int barid = 1 + half;

    // ---- prefetch A (once, whole CTA): 16KB, 4 chunks/thread ----
    {
        const __half* gA = g_A + (size_t)(w * NKP + kh * 128) * CK;
        #pragma unroll
        for (int i = 0; i < 4; i++) {
            int ch = tid + i * 256;
            int row = ch >> 3, c = ch & 7;
            const __half* src = gA + row * CK + c * 8;
            uint32_t dst = sb + SM_A + row * 128 + (((c ^ (row & 7))) << 4);
            CP16(dst, (const void*)src);
        }
    }
    const __half* gB = g_B + (size_t)b * HW * CK;
    auto prefB = [&](int buf, int t) {
        #pragma unroll
        for (int i = 0; i < 4; i++) {
            int ch = h + i * 128;                  // 0..511
            int row = ch >> 3, c = ch & 7;
            const __half* src = gB + (size_t)(t * TPX + n0 + row) * CK + c * 8;
            uint32_t dst = sb + SM_B(half, buf) + row * 128 + (((c ^ (row & 7))) << 4);
            CP16(dst, (const void*)src);
        }
    };
    prefB(0, t0);
    CP_COMMIT();

    // ---- per-warp fragment addressing ----
    int m0 = (wid & 3) * 32;
    int aRow = (lane & 7) + ((lane >> 3) & 1) * 8;
    int aCh  = (lane >> 4) & 1;
    int bRow = (lane & 7) + ((lane >> 4) & 1) * 8;
    int bCh  = (lane >> 3) & 1;
    int rA0 = m0 + aRow, rA1 = rA0 + 16;
    uint32_t aB0 = sb + SM_A + rA0 * 128, aB1 = sb + SM_A + rA1 * 128;
    int xA0 = rA0 & 7, xA1 = rA1 & 7;
    uint32_t bOff[4]; int xB[4];
    #pragma unroll
    for (int q = 0; q < 4; q++) {
        int rB = q * 16 + bRow;
        bOff[q] = rB * 128; xB[q] = rB & 7;
    }
    int g = lane >> 2, t4 = lane & 3;
    const float K1 = 144.2695041f;                 // 100 * log2(e)
    float t4f2 = (float)(n0 + t4 * 2);

    // cross-tile accumulators
    float sA[2][2] = {{0.f,0.f},{0.f,0.f}};
    float uA[2][2] = {{0.f,0.f},{0.f,0.f}};
    float vA[2][2] = {{0.f,0.f},{0.f,0.f}};

    int buf = 0;
    for (int t = t0; t < t1; t++) {
        if (t + 1 < t1) prefB(buf ^ 1, t + 1);
        CP_COMMIT();
        CP_WAIT1();
        if (t == t0) __syncthreads();              // A + B(t0) visibility
        else BARH(barid);                          // B(t) visibility within half

        float acc[2][8][4];
        #pragma unroll
        for (int i = 0; i < 2; i++)
            #pragma unroll
            for (int nt = 0; nt < 8; nt++)
                #pragma unroll
                for (int q = 0; q < 4; q++) acc[i][nt][q] = 0.f;

        uint32_t bB = sb + SM_B(half, buf);
        #pragma unroll
        for (int ks = 0; ks < 4; ks++) {
            uint32_t Af0[4], Af1[4], Bf[4][4];
            int chA = aCh + 2 * ks;
            int chB = bCh + 2 * ks;
            LDSM4(Af0, aB0 + ((chA ^ xA0) << 4));
            LDSM4(Af1, aB1 + ((chA ^ xA1) << 4));
            #pragma unroll
            for (int q = 0; q < 4; q++) LDSM4(Bf[q], bB + bOff[q] + ((chB ^ xB[q]) << 4));
            #pragma unroll
            for (int nt = 0; nt < 8; nt++) {
                uint32_t b0 = Bf[nt >> 1][(nt & 1) * 2];
                uint32_t b1 = Bf[nt >> 1][(nt & 1) * 2 + 1];
                MMA16816(acc[0][nt], Af0, b0, b1);
                MMA16816(acc[1][nt], Af1, b0, b1);
            }
        }

        BARH(barid);       // release buf (epilogue is reg-private)

        // ---- epilogue: per-tile (s,u) then fold into cross-tile accumulators ----
        float uoff = (float)((t & 1) * 128);       // global-u tile offset
        float vt = (float)(t >> 1);                // v constant for this tile
        #pragma unroll
        for (int mt = 0; mt < 2; mt++) {
            float s0 = 0.f, m0f = 0.f, o0 = 0.f;
            float s1 = 0.f, m1f = 0.f, o1 = 0.f;
            #pragma unroll
            for (int nt = 0; nt < 8; nt++) {
                float ntf = (float)nt;
                float e0, e1, e2, e3;
                asm("ex2.approx.ftz.f32 %0, %1;" : "=f"(e0) : "f"(fmaf(acc[mt][nt][0], K1, -K1)));
                asm("ex2.approx.ftz.f32 %0, %1;" : "=f"(e1) : "f"(fmaf(acc[mt][nt][1], K1, -K1)));
                asm("ex2.approx.ftz.f32 %0, %1;" : "=f"(e2) : "f"(fmaf(acc[mt][nt][2], K1, -K1)));
                asm("ex2.approx.ftz.f32 %0, %1;" : "=f"(e3) : "f"(fmaf(acc[mt][nt][3], K1, -K1)));
                float p0 = e0 + e1, p1 = e2 + e3;
                s0 += p0;  m0f = fmaf(ntf, p0, m0f);  o0 += e1;
                s1 += p1;  m1f = fmaf(ntf, p1, m1f);  o1 += e3;
            }
            float u0 = fmaf(8.f, m0f, o0); u0 = fmaf(t4f2 + uoff, s0, u0);
            float u1 = fmaf(8.f, m1f, o1); u1 = fmaf(t4f2 + uoff, s1, u1);
            sA[mt][0] += s0;  uA[mt][0] += u0;  vA[mt][0] = fmaf(vt, s0, vA[mt][0]);
            sA[mt][1] += s1;  uA[mt][1] += u1;  vA[mt][1] = fmaf(vt, s1, vA[mt][1]);
        }
        buf ^= 1;
    }

    // ---- single final reduce across the 4 t4-lanes + store ----
    #pragma unroll
    for (int mt = 0; mt < 2; mt++) {
        #pragma unroll
        for (int sr = 0; sr < 2; sr++) {
            float s = sA[mt][sr], u = uA[mt][sr], v = vA[mt][sr];
            #pragma unroll
            for (int d = 1; d <= 2; d <<= 1) {
                s += __shfl_xor_sync(0xFFFFFFFF, s, d);
                u += __shfl_xor_sync(0xFFFFFFFF, u, d);
                v += __shfl_xor_sync(0xFFFFFFFF, v, d);
            }
            if (t4 == 0) {
                int r = m0 + mt * 16 + sr * 8 + g;
                size_t row = (size_t)w * NKP + kh * 128 + r;
                g_part[row * NPART + j * 2 + half] = make_float4(s, u, v, 0.f);
            }
        }
    }
}

// ---------------------------------------------------------------- reduce + tail merged
__global__ __launch_bounds__(256) void k_finish(const float* __restrict__ scores,
                                                float* __restrict__ out) {
    if (blockIdx.x < 192) {
        int row = blockIdx.x * 8 + (threadIdx.x >> 5);
        int lane = threadIdx.x & 31;
        const float4* p = g_part + (size_t)row * NPART;
        float s = 0.f, u = 0.f, v = 0.f;
        #pragma unroll
        for (int i = 0; i < 4; i++) {
            int idx = lane + i * 32;
            if (idx < NPART) {
                float4 q = p[idx];
                s += q.x; u += q.y; v += q.z;
            }
        }
        #pragma unroll
        for (int d = 16; d > 0; d >>= 1) {
            s += __shfl_xor_sync(0xFFFFFFFF, s, d);
            u += __shfl_xor_sync(0xFFFFFFFF, u, d);
            v += __shfl_xor_sync(0xFFFFFFFF, v, d);
        }
        if (lane == 0) {
            float inv = 1.f / s;
            out[row * 2 + 0] = u * inv;
            out[row * 2 + 1] = v * inv;
        }
    } else {
        int w = blockIdx.x - 192, n = threadIdx.x;
        int f = (w / 3) * 4 + (w % 3) + 1;
        out[3072 + w * NKP + n] = scores[f * NKP + n];
        if (n == 0) {
            out[4608 + w] = (float)f;
            out[4614 + w] = (float)((w / 3) * 4);
        }
    }
}

extern "C" void kernel_launch(void* const* d_in, const int* in_sizes, int n_in,
                              void* d_out, int out_size) {
    (void)in_sizes; (void)n_in; (void)out_size;
    const float* scores = (const float*)d_in[0];
    const float* kd     = (const float*)d_in[1];
    const float* dd     = (const float*)d_in[2];
    float* out = (float*)d_out;

    cudaFuncSetAttribute(k_gemm, cudaFuncAttributeMaxDynamicSharedMemorySize, SM_TOT);

    k_prep_tgt<<<NGRP, 128>>>(kd);          // launch 0
    k_prep_src<<<512, 128>>>(dd, 0);        // launch 1
    k_prep_src<<<512, 128>>>(dd, 512);      // launch 2
    k_gemm<<<NCTA, 256, SM_TOT>>>();        // launch 3  (ncu lands here)
    k_finish<<<198, 256>>>(scores, out);    // launch 4
}